// round 8
// baseline (speedup 1.0000x reference)
#include <cuda_runtime.h>
#include <cuda_fp16.h>
#include <math.h>
#include <stdint.h>

#define CCH 512
#define ND  512
#define HWV 4096
#define NPX 65536
#define MT  64
#define KCH 32
#define TOTCH 32          // 2 n-tiles (256n) * 16 k-chunks
#define THREADS 256
#define MARGIN 1e-5f

#define SW64(o) ((o) ^ (((o) >> 3) & 0x30))

typedef unsigned int u32;

// ---------------- device scratch ----------------
__device__ __align__(16) __half g_Bhi[ND * CCH];
__device__ __align__(16) __half g_Blo[ND * CCH];
__device__ float g_dnorm[ND * CCH];

// ---------------- PTX helpers ----------------
__device__ __forceinline__ u32 smem_u32(const void* p) {
    u32 a;
    asm("{ .reg .u64 t; cvta.to.shared.u64 t, %1; cvt.u32.u64 %0, t; }" : "=r"(a) : "l"(p));
    return a;
}
#define CP16(dst, src) \
    asm volatile("cp.async.cg.shared.global [%0], [%1], 16;" :: "r"(dst), "l"(src) : "memory")
#define CP_COMMIT() asm volatile("cp.async.commit_group;" ::: "memory")
#define CP_WAIT1()  asm volatile("cp.async.wait_group 1;" ::: "memory")

#define LDSM4(r, addr) \
    asm volatile("ldmatrix.sync.aligned.m8n8.x4.shared.b16 {%0,%1,%2,%3}, [%4];" \
        : "=r"((r)[0]), "=r"((r)[1]), "=r"((r)[2]), "=r"((r)[3]) : "r"(addr))

#define MMA16816(d, a, b0, b1) \
    asm volatile("mma.sync.aligned.m16n8k16.row.col.f32.f16.f16.f32 " \
        "{%0,%1,%2,%3},{%4,%5,%6,%7},{%8,%9},{%0,%1,%2,%3};" \
        : "+f"((d)[0]), "+f"((d)[1]), "+f"((d)[2]), "+f"((d)[3]) \
        : "r"((a)[0]), "r"((a)[1]), "r"((a)[2]), "r"((a)[3]), "r"(b0), "r"(b1))

#define STS128(addr, v) \
    asm volatile("st.shared.v4.b32 [%0], {%1,%2,%3,%4};" \
        :: "r"(addr), "r"((v).x), "r"((v).y), "r"((v).z), "r"((v).w) : "memory")

// ---------------- prep: dict -> dnorm fp32 + fp16 hi/lo [n][k] --------------
__global__ void prep_dict(const float* __restrict__ dict) {
    int n = blockIdx.x;
    const float* row = dict + n * CCH;
    float s = 0.f;
    for (int k = threadIdx.x; k < CCH; k += 128) {
        float v = row[k];
        s = fmaf(v, v, s);
    }
#pragma unroll
    for (int o = 16; o; o >>= 1) s += __shfl_xor_sync(0xffffffffu, s, o);
    __shared__ float red[4];
    if ((threadIdx.x & 31) == 0) red[threadIdx.x >> 5] = s;
    __syncthreads();
    float norm = sqrtf(red[0] + red[1] + red[2] + red[3]);
    for (int k = threadIdx.x; k < CCH; k += 128) {
        float v = row[k] / norm;
        g_dnorm[n * CCH + k] = v;
        __half h = __float2half(v);
        g_Bhi[n * CCH + k] = h;
        g_Blo[n * CCH + k] = __float2half(v - __half2float(h));
    }
}

// reduction / staging overlays (aliased onto the A smem region after the GEMM)
struct Red {
    float bv1[MT][4]; float bv2[MT][4];
    int   bi1[MT][4]; int   bi2[MT][4];
};

// ---------------- main: fused convert + persistent-A split-fp16 GEMM --------
__global__ void __launch_bounds__(THREADS, 1)
negdict_mma(const float* __restrict__ x, const float* __restrict__ dict,
            float* __restrict__ out) {
    // dyn smem: Ahi 64KB | Alo 64KB | B ring 3 x 32KB  = 224KB
    extern __shared__ __align__(16) char dsm[];
    __shared__ float s_negq[MT];
    __shared__ int s_idx[MT];
    __shared__ int s_rep[MT];

    const int tid = threadIdx.x;
    const int wid = tid >> 5;
    const int lid = tid & 31;
    const int wm = wid >> 2;          // 0..1 : 32 px each
    const int wn = wid & 3;           // 0..3 : 64 n each (per n-tile pass)
    const int pxbase = blockIdx.x * MT;
    const int b = pxbase >> 12;
    const int hw0 = pxbase & 4095;
    const float* xb = x + (size_t)b * CCH * HWV + hw0;

    const u32 sA = smem_u32(dsm);              // hi tiles: 16 x 4KB
    const u32 sAlo = sA + 65536;               // lo tiles
    const u32 sB = sA + 131072;                // ring: buf*32KB (hi 16KB | lo 16KB)

    // ldmatrix lane offsets (A tile: 64px x 32k, 64B rows; B tile: 256n x 32k)
    u32 offA[2], offB[4];
#pragma unroll
    for (int t = 0; t < 2; t++) {
        int rowA = wm * 32 + t * 16 + (lid & 7) + 8 * ((lid >> 3) & 1);
        offA[t] = SW64((u32)(rowA * 64 + ((lid >> 4) << 4)));
    }
#pragma unroll
    for (int g = 0; g < 4; g++) {
        int rowB = wn * 64 + g * 16 + (lid & 7) + 8 * (lid >> 4);
        offB[g] = SW64((u32)(rowB * 64 + (((lid >> 3) & 1) << 4)));
    }

    float acc[2][8][4];
#pragma unroll
    for (int t = 0; t < 2; t++)
#pragma unroll
        for (int j = 0; j < 8; j++)
#pragma unroll
            for (int q = 0; q < 4; q++) acc[t][j][q] = 0.f;

    float bv1s[4], bv2s[4];
    int bi1s[4], bi2s[4];
#pragma unroll
    for (int s = 0; s < 4; s++) {
        bv1s[s] = -1e30f; bv2s[s] = -1e30f;
        bi1s[s] = 0x7fffffff; bi2s[s] = 0x7fffffff;
    }
    float ssqf[4] = {0.f, 0.f, 0.f, 0.f};

    // x prefetch mapping: px = tid&63, kh = tid>>6 (8 k each)
    const int px_l = tid & 63;
    const int kh = tid >> 6;
    float xr[8];

    auto ldx = [&](int cc) {
        int k0 = (cc & 15) * KCH + kh * 8;
#pragma unroll
        for (int i = 0; i < 8; i++) xr[i] = xb[(size_t)(k0 + i) * HWV + px_l];
    };
    auto cvtsts = [&](int cc) {
        union { __half2 h2[4]; uint4 v; } hi, lo;
#pragma unroll
        for (int i = 0; i < 4; i++) {
            __half h0 = __float2half(xr[2 * i]);
            __half h1 = __float2half(xr[2 * i + 1]);
            hi.h2[i] = __halves2half2(h0, h1);
            lo.h2[i] = __halves2half2(
                __float2half(xr[2 * i]     - __half2float(h0)),
                __float2half(xr[2 * i + 1] - __half2float(h1)));
        }
        u32 dst = (u32)((cc & 15) * 4096) + SW64((u32)(px_l * 64 + kh * 16));
        STS128(sA + dst, hi.v);
        STS128(sAlo + dst, lo.v);
    };
    auto issueB = [&](int cc) {
        u32 bufb = sB + (cc % 3) * 32768;
        int nt = cc >> 4;
        int kc = (cc & 15) * KCH;
        int r = tid;                    // 0..255 n-rows
#pragma unroll
        for (int g = 0; g < 4; g++) {
            u32 dsw = SW64((u32)(r * 64 + g * 16));
            size_t boff = (size_t)(nt * 256 + r) * CCH + kc + g * 8;
            CP16(bufb + dsw,         g_Bhi + boff);
            CP16(bufb + 16384 + dsw, g_Blo + boff);
        }
        CP_COMMIT();
    };

    // prologue: build A tile 0, start B pipeline (2 bufs in flight)
    ldx(0);
    issueB(0); issueB(1);
    cvtsts(0);

    for (int cc = 0; cc < TOTCH; cc++) {
        CP_WAIT1();
        __syncthreads();
        if (cc + 2 < TOTCH) issueB(cc + 2);
        if (cc + 1 < 16) ldx(cc + 1);

        const u32 abase = sA + (cc & 15) * 4096;
        const u32 albase = sAlo + (cc & 15) * 4096;
        const u32 bbase = sB + (cc % 3) * 32768;

        __half2 cA[2], cB[2];
        cA[0] = cA[1] = cB[0] = cB[1] = __halves2half2(__float2half(0.f), __float2half(0.f));

#pragma unroll
        for (int s = 0; s < 2; s++) {
            u32 kx = (u32)(s << 5);
            u32 Ah[2][4], Al[2][4], Bh[4][4], Bl[4][4];
#pragma unroll
            for (int t = 0; t < 2; t++) {
                LDSM4(Ah[t], abase + (offA[t] ^ kx));
                LDSM4(Al[t], albase + (offA[t] ^ kx));
            }
#pragma unroll
            for (int g = 0; g < 4; g++) {
                LDSM4(Bh[g], bbase + (offB[g] ^ kx));
                LDSM4(Bl[g], bbase + 16384 + (offB[g] ^ kx));
            }
            if (cc < 16 && wn == 0) {       // ||x||^2 from hi fragments (pass 0)
#pragma unroll
                for (int t = 0; t < 2; t++) {
                    __half2 a0 = *(__half2*)&Ah[t][0];
                    __half2 a2 = *(__half2*)&Ah[t][2];
                    __half2 a1 = *(__half2*)&Ah[t][1];
                    __half2 a3 = *(__half2*)&Ah[t][3];
                    cA[t] = __hfma2(a0, a0, cA[t]);
                    cA[t] = __hfma2(a2, a2, cA[t]);
                    cB[t] = __hfma2(a1, a1, cB[t]);
                    cB[t] = __hfma2(a3, a3, cB[t]);
                }
            }
#pragma unroll
            for (int t = 0; t < 2; t++)
#pragma unroll
                for (int j = 0; j < 8; j++)
                    MMA16816(acc[t][j], Ah[t], Bh[j >> 1][(j & 1) * 2], Bh[j >> 1][(j & 1) * 2 + 1]);
#pragma unroll
            for (int t = 0; t < 2; t++)
#pragma unroll
                for (int j = 0; j < 8; j++)
                    MMA16816(acc[t][j], Ah[t], Bl[j >> 1][(j & 1) * 2], Bl[j >> 1][(j & 1) * 2 + 1]);
#pragma unroll
            for (int t = 0; t < 2; t++)
#pragma unroll
                for (int j = 0; j < 8; j++)
                    MMA16816(acc[t][j], Al[t], Bh[j >> 1][(j & 1) * 2], Bh[j >> 1][(j & 1) * 2 + 1]);
        }

        if (cc < 16 && wn == 0) {
#pragma unroll
            for (int t = 0; t < 2; t++) {
                ssqf[2 * t]     += __low2float(cA[t]) + __high2float(cA[t]);
                ssqf[2 * t + 1] += __low2float(cB[t]) + __high2float(cB[t]);
            }
        }
        if (cc + 1 < 16) cvtsts(cc + 1);

        if ((cc & 15) == 15) {              // fold n-tile (256n) into per-lane top-2
            int nt = cc >> 4;
            int nbase = nt * 256 + wn * 64;
#pragma unroll
            for (int j = 0; j < 8; j++) {
                int nb = nbase + (j >> 1) * 16 + (j & 1) * 8 + 2 * (lid & 3);
#pragma unroll
                for (int t = 0; t < 2; t++) {
#pragma unroll
                    for (int q = 0; q < 4; q++) {
                        int s = 2 * t + (q >> 1);
                        int n = nb + (q & 1);
                        float v = acc[t][j][q];
                        if (v > bv1s[s]) {
                            bv2s[s] = bv1s[s]; bi2s[s] = bi1s[s];
                            bv1s[s] = v;       bi1s[s] = n;
                        } else if (v > bv2s[s]) {
                            bv2s[s] = v; bi2s[s] = n;
                        }
                        acc[t][j][q] = 0.f;
                    }
                }
            }
        }
    }

    // ---------------- negq --------------------------------------------------
    if (wn == 0) {
#pragma unroll
        for (int s = 0; s < 4; s++) {
            float v = ssqf[s];
            v += __shfl_xor_sync(0xffffffffu, v, 1);
            v += __shfl_xor_sync(0xffffffffu, v, 2);
            ssqf[s] = v;
        }
        if ((lid & 3) == 0) {
#pragma unroll
            for (int t = 0; t < 2; t++) {
                int p = wm * 32 + t * 16 + (lid >> 2);
                s_negq[p]     = -0.25f * sqrtf(ssqf[2 * t]);
                s_negq[p + 8] = -0.25f * sqrtf(ssqf[2 * t + 1]);
            }
        }
    }

    // ---------------- warp-level top-2 merge across lid&3 lanes -------------
#pragma unroll
    for (int s = 0; s < 4; s++) {
#pragma unroll
        for (int o = 1; o <= 2; o <<= 1) {
            float ov1 = __shfl_xor_sync(0xffffffffu, bv1s[s], o);
            float ov2 = __shfl_xor_sync(0xffffffffu, bv2s[s], o);
            int   oi1 = __shfl_xor_sync(0xffffffffu, bi1s[s], o);
            int   oi2 = __shfl_xor_sync(0xffffffffu, bi2s[s], o);
            if (ov1 > bv1s[s] || (ov1 == bv1s[s] && oi1 < bi1s[s])) {
                bv2s[s] = bv1s[s]; bi2s[s] = bi1s[s];
                bv1s[s] = ov1;     bi1s[s] = oi1;
            } else if (ov1 > bv2s[s] || (ov1 == bv2s[s] && oi1 < bi2s[s])) {
                bv2s[s] = ov1; bi2s[s] = oi1;
            }
            if (ov2 > bv2s[s] || (ov2 == bv2s[s] && oi2 < bi2s[s])) {
                bv2s[s] = ov2; bi2s[s] = oi2;
            }
        }
    }
    __syncthreads();    // GEMM fully done: A smem region now reusable
    Red* red = (Red*)dsm;
    if ((lid & 3) == 0) {
#pragma unroll
        for (int t = 0; t < 2; t++)
#pragma unroll
            for (int h = 0; h < 2; h++) {
                int s = 2 * t + h;
                int p = wm * 32 + t * 16 + (lid >> 2) + 8 * h;
                red->bv1[p][wn] = bv1s[s];
                red->bv2[p][wn] = bv2s[s];
                red->bi1[p][wn] = bi1s[s];
                red->bi2[p][wn] = bi2s[s];
            }
    }
    __syncthreads();

    if (tid < MT) {
        float B1 = -1e30f, B2 = -1e30f;
        int I1 = 0x7fffffff, I2 = 0x7fffffff;
#pragma unroll
        for (int col = 0; col < 4; col++) {
#pragma unroll
            for (int w = 0; w < 2; w++) {
                float v = w ? red->bv2[tid][col] : red->bv1[tid][col];
                int   i = w ? red->bi2[tid][col] : red->bi1[tid][col];
                if (v > B1 || (v == B1 && i < I1)) {
                    B2 = B1; I2 = I1; B1 = v; I1 = i;
                } else if (v > B2 || (v == B2 && i < I2)) {
                    B2 = v; I2 = i;
                }
            }
        }
        int bi = I1;
        if (B1 - B2 < MARGIN) {
            const float* xp = xb + tid;
            const float* d1 = g_dnorm + (size_t)I1 * CCH;
            const float* d2 = g_dnorm + (size_t)I2 * CCH;
            float s1 = 0.f, s2 = 0.f;
            for (int k = 0; k < CCH; k++) {
                float xv = xp[(size_t)k * HWV];
                s1 = fmaf(xv, d1[k], s1);
                s2 = fmaf(xv, d2[k], s2);
            }
            if (s2 > s1 || (s2 == s1 && I2 < I1)) bi = I2;
        }
        s_idx[tid] = bi;
        s_rep[tid] = (B1 > s_negq[tid]) ? 1 : 0;
    }
    __syncthreads();

    // ---------------- epilogue: gather + blend + coalesced writes ------------
    float (*rows)[65] = (float (*)[65])dsm;   // aliases A region (free now)
    float* outb = out + (size_t)b * CCH * HWV + hw0;
    for (int c0 = 0; c0 < CCH; c0 += 64) {
#pragma unroll
        for (int it = 0; it < 4; it++) {
            int lin = it * THREADS + tid;   // over [p:64][cq:16]
            int p = lin >> 4;
            int cq = (lin & 15) * 4;
            float4 v = *(const float4*)(dict + (size_t)s_idx[p] * CCH + c0 + cq);
            rows[p][cq + 0] = v.x;
            rows[p][cq + 1] = v.y;
            rows[p][cq + 2] = v.z;
            rows[p][cq + 3] = v.w;
        }
        __syncthreads();
#pragma unroll
        for (int it = 0; it < 16; it++) {
            int lin = it * THREADS + tid;   // over [c:64][p:64]
            int c = c0 + (lin >> 6);
            int p = lin & 63;
            float v = rows[p][c - c0];
            if (!s_rep[p]) v = xb[(size_t)c * HWV + p];
            outb[(size_t)c * HWV + p] = v;
        }
        __syncthreads();
    }
}

// ---------------- launch ------------------------------------------------------
extern "C" void kernel_launch(void* const* d_in, const int* in_sizes, int n_in,
                              void* d_out, int out_size) {
    const float* x;
    const float* nd;
    if (n_in >= 2 && in_sizes[0] == ND * CCH && in_sizes[1] != ND * CCH) {
        nd = (const float*)d_in[0];
        x  = (const float*)d_in[1];
    } else {
        x  = (const float*)d_in[0];
        nd = (const float*)d_in[1];
    }
    float* out = (float*)d_out;

    cudaFuncSetAttribute(negdict_mma, cudaFuncAttributeMaxDynamicSharedMemorySize,
                         229376);

    prep_dict<<<ND, 128>>>(nd);
    negdict_mma<<<NPX / MT, THREADS, 229376>>>(x, nd, out);
}

// round 9
// speedup vs baseline: 1.2488x; 1.2488x over previous
#include <cuda_runtime.h>
#include <cuda_fp16.h>
#include <math.h>
#include <stdint.h>

#define CCH 512
#define ND  512
#define HWV 4096
#define NPX 65536
#define MT  64
#define KCH 32
#define TOTCH 32          // 2 n-passes (256n) * 16 k-chunks
#define THREADS 512
#define MARGIN 1e-5f

#define SW64(o) ((o) ^ (((o) >> 3) & 0x30))

typedef unsigned int u32;

// ---------------- device scratch ----------------
__device__ __align__(16) __half g_Bhi[ND * CCH];
__device__ __align__(16) __half g_Blo[ND * CCH];
__device__ float g_dnorm[ND * CCH];

// ---------------- PTX helpers ----------------
__device__ __forceinline__ u32 smem_u32(const void* p) {
    u32 a;
    asm("{ .reg .u64 t; cvta.to.shared.u64 t, %1; cvt.u32.u64 %0, t; }" : "=r"(a) : "l"(p));
    return a;
}
#define CP16(dst, src) \
    asm volatile("cp.async.cg.shared.global [%0], [%1], 16;" :: "r"(dst), "l"(src) : "memory")
#define CP_COMMIT() asm volatile("cp.async.commit_group;" ::: "memory")
#define CP_WAIT1()  asm volatile("cp.async.wait_group 1;" ::: "memory")

#define LDSM4(r, addr) \
    asm volatile("ldmatrix.sync.aligned.m8n8.x4.shared.b16 {%0,%1,%2,%3}, [%4];" \
        : "=r"((r)[0]), "=r"((r)[1]), "=r"((r)[2]), "=r"((r)[3]) : "r"(addr))

#define MMA16816(d, a, b0, b1) \
    asm volatile("mma.sync.aligned.m16n8k16.row.col.f32.f16.f16.f32 " \
        "{%0,%1,%2,%3},{%4,%5,%6,%7},{%8,%9},{%0,%1,%2,%3};" \
        : "+f"((d)[0]), "+f"((d)[1]), "+f"((d)[2]), "+f"((d)[3]) \
        : "r"((a)[0]), "r"((a)[1]), "r"((a)[2]), "r"((a)[3]), "r"(b0), "r"(b1))

#define STS128(addr, v) \
    asm volatile("st.shared.v4.b32 [%0], {%1,%2,%3,%4};" \
        :: "r"(addr), "r"((v).x), "r"((v).y), "r"((v).z), "r"((v).w) : "memory")

// ---------------- prep: dict -> dnorm fp32 + fp16 hi/lo [n][k] --------------
__global__ void prep_dict(const float* __restrict__ dict) {
    int n = blockIdx.x;
    const float* row = dict + n * CCH;
    float s = 0.f;
    for (int k = threadIdx.x; k < CCH; k += 128) {
        float v = row[k];
        s = fmaf(v, v, s);
    }
#pragma unroll
    for (int o = 16; o; o >>= 1) s += __shfl_xor_sync(0xffffffffu, s, o);
    __shared__ float red[4];
    if ((threadIdx.x & 31) == 0) red[threadIdx.x >> 5] = s;
    __syncthreads();
    float norm = sqrtf(red[0] + red[1] + red[2] + red[3]);
    for (int k = threadIdx.x; k < CCH; k += 128) {
        float v = row[k] / norm;
        g_dnorm[n * CCH + k] = v;
        __half h = __float2half(v);
        g_Bhi[n * CCH + k] = h;
        g_Blo[n * CCH + k] = __float2half(v - __half2float(h));
    }
}

// reduction overlay (aliased onto the A smem region after the GEMM)
struct Red {
    float bv1[MT][8]; float bv2[MT][8];
    int   bi1[MT][8]; int   bi2[MT][8];
};

// ---------------- main: fused convert + persistent-A split-fp16 GEMM --------
__global__ void __launch_bounds__(THREADS, 1)
negdict_mma(const float* __restrict__ x, const float* __restrict__ dict,
            float* __restrict__ out) {
    // dyn smem: Ahi 64KB | Alo 64KB | B ring 3 x 32KB  = 224KB
    extern __shared__ __align__(16) char dsm[];
    __shared__ float s_negq[MT];
    __shared__ int s_idx[MT];
    __shared__ int s_rep[MT];

    const int tid = threadIdx.x;
    const int wid = tid >> 5;
    const int lid = tid & 31;
    const int wm = wid >> 3;          // 0..1 : 32 px each
    const int wn = wid & 7;           // 0..7 : 32 n each (per n-pass)
    const int pxbase = blockIdx.x * MT;
    const int b = pxbase >> 12;
    const int hw0 = pxbase & 4095;
    const float* xb = x + (size_t)b * CCH * HWV + hw0;

    const u32 sA = smem_u32(dsm);              // hi tiles: 16 x 4KB
    const u32 sAlo = sA + 65536;               // lo tiles
    const u32 sB = sA + 131072;                // ring: buf*32KB (hi 16KB | lo 16KB)

    // ldmatrix lane offsets (A tile: 64px x 32k, 64B rows; B tile: 256n x 32k)
    u32 offA[2], offB[2];
#pragma unroll
    for (int t = 0; t < 2; t++) {
        int rowA = wm * 32 + t * 16 + (lid & 7) + 8 * ((lid >> 3) & 1);
        offA[t] = SW64((u32)(rowA * 64 + ((lid >> 4) << 4)));
    }
#pragma unroll
    for (int g = 0; g < 2; g++) {
        int rowB = wn * 32 + g * 16 + (lid & 7) + 8 * (lid >> 4);
        offB[g] = SW64((u32)(rowB * 64 + (((lid >> 3) & 1) << 4)));
    }

    float acc[2][4][4];
#pragma unroll
    for (int t = 0; t < 2; t++)
#pragma unroll
        for (int j = 0; j < 4; j++)
#pragma unroll
            for (int q = 0; q < 4; q++) acc[t][j][q] = 0.f;

    float bv1s[4], bv2s[4];
    int bi1s[4], bi2s[4];
#pragma unroll
    for (int s = 0; s < 4; s++) {
        bv1s[s] = -1e30f; bv2s[s] = -1e30f;
        bi1s[s] = 0x7fffffff; bi2s[s] = 0x7fffffff;
    }
    float ssqf[4] = {0.f, 0.f, 0.f, 0.f};

    // x prefetch mapping (tid<256): px = tid&63, kh = (tid>>6)&3 (8 k each)
    const int px_l = tid & 63;
    const int kh = (tid >> 6) & 3;
    const bool xload = (tid < 256);
    float xr[8];

    auto ldx = [&](int cc) {
        if (!xload) return;
        int k0 = (cc & 15) * KCH + kh * 8;
#pragma unroll
        for (int i = 0; i < 8; i++) xr[i] = xb[(size_t)(k0 + i) * HWV + px_l];
    };
    auto cvtsts = [&](int cc) {
        if (!xload) return;
        union { __half2 h2[4]; uint4 v; } hi, lo;
#pragma unroll
        for (int i = 0; i < 4; i++) {
            __half h0 = __float2half(xr[2 * i]);
            __half h1 = __float2half(xr[2 * i + 1]);
            hi.h2[i] = __halves2half2(h0, h1);
            lo.h2[i] = __halves2half2(
                __float2half(xr[2 * i]     - __half2float(h0)),
                __float2half(xr[2 * i + 1] - __half2float(h1)));
        }
        u32 dst = (u32)((cc & 15) * 4096) + SW64((u32)(px_l * 64 + kh * 16));
        STS128(sA + dst, hi.v);
        STS128(sAlo + dst, lo.v);
    };
    auto issueB = [&](int cc) {
        u32 bufb = sB + (cc % 3) * 32768;
        int nt = cc >> 4;
        int kc = (cc & 15) * KCH;
        int r = tid >> 1;               // 0..255 n-rows
        int g2 = (tid & 1) * 2;
#pragma unroll
        for (int gg = 0; gg < 2; gg++) {
            int g = g2 + gg;
            u32 dsw = SW64((u32)(r * 64 + g * 16));
            size_t boff = (size_t)(nt * 256 + r) * CCH + kc + g * 8;
            CP16(bufb + dsw,         g_Bhi + boff);
            CP16(bufb + 16384 + dsw, g_Blo + boff);
        }
        CP_COMMIT();
    };

    // prologue: build A tile 0, start B pipeline (2 bufs in flight)
    ldx(0);
    issueB(0); issueB(1);
    cvtsts(0);

    for (int cc = 0; cc < TOTCH; cc++) {
        CP_WAIT1();
        __syncthreads();
        if (cc + 2 < TOTCH) issueB(cc + 2);
        if (cc + 1 < 16) ldx(cc + 1);

        const u32 abase = sA + (cc & 15) * 4096;
        const u32 albase = sAlo + (cc & 15) * 4096;
        const u32 bbase = sB + (cc % 3) * 32768;

        __half2 cA[2], cB[2];
        cA[0] = cA[1] = cB[0] = cB[1] = __halves2half2(__float2half(0.f), __float2half(0.f));

#pragma unroll
        for (int s = 0; s < 2; s++) {
            u32 kx = (u32)(s << 5);
            u32 Ah[2][4], Al[2][4], Bh[2][4], Bl[2][4];
#pragma unroll
            for (int t = 0; t < 2; t++) {
                LDSM4(Ah[t], abase + (offA[t] ^ kx));
                LDSM4(Al[t], albase + (offA[t] ^ kx));
            }
#pragma unroll
            for (int g = 0; g < 2; g++) {
                LDSM4(Bh[g], bbase + (offB[g] ^ kx));
                LDSM4(Bl[g], bbase + 16384 + (offB[g] ^ kx));
            }
            if (cc < 16 && wn == 0) {       // ||x||^2 from hi fragments (n-pass 0)
#pragma unroll
                for (int t = 0; t < 2; t++) {
                    __half2 a0 = *(__half2*)&Ah[t][0];
                    __half2 a2 = *(__half2*)&Ah[t][2];
                    __half2 a1 = *(__half2*)&Ah[t][1];
                    __half2 a3 = *(__half2*)&Ah[t][3];
                    cA[t] = __hfma2(a0, a0, cA[t]);
                    cA[t] = __hfma2(a2, a2, cA[t]);
                    cB[t] = __hfma2(a1, a1, cB[t]);
                    cB[t] = __hfma2(a3, a3, cB[t]);
                }
            }
#pragma unroll
            for (int t = 0; t < 2; t++)
#pragma unroll
                for (int j = 0; j < 4; j++)
                    MMA16816(acc[t][j], Ah[t], Bh[j >> 1][(j & 1) * 2], Bh[j >> 1][(j & 1) * 2 + 1]);
#pragma unroll
            for (int t = 0; t < 2; t++)
#pragma unroll
                for (int j = 0; j < 4; j++)
                    MMA16816(acc[t][j], Ah[t], Bl[j >> 1][(j & 1) * 2], Bl[j >> 1][(j & 1) * 2 + 1]);
#pragma unroll
            for (int t = 0; t < 2; t++)
#pragma unroll
                for (int j = 0; j < 4; j++)
                    MMA16816(acc[t][j], Al[t], Bh[j >> 1][(j & 1) * 2], Bh[j >> 1][(j & 1) * 2 + 1]);
        }

        if (cc < 16 && wn == 0) {
#pragma unroll
            for (int t = 0; t < 2; t++) {
                ssqf[2 * t]     += __low2float(cA[t]) + __high2float(cA[t]);
                ssqf[2 * t + 1] += __low2float(cB[t]) + __high2float(cB[t]);
            }
        }
        if (cc + 1 < 16) cvtsts(cc + 1);

        if ((cc & 15) == 15) {              // fold n-pass (256n) into per-lane top-2
            int nt = cc >> 4;
            int nbase = nt * 256 + wn * 32;
#pragma unroll
            for (int j = 0; j < 4; j++) {
                int nb = nbase + (j >> 1) * 16 + (j & 1) * 8 + 2 * (lid & 3);
#pragma unroll
                for (int t = 0; t < 2; t++) {
#pragma unroll
                    for (int q = 0; q < 4; q++) {
                        int s = 2 * t + (q >> 1);
                        int n = nb + (q & 1);
                        float v = acc[t][j][q];
                        if (v > bv1s[s]) {
                            bv2s[s] = bv1s[s]; bi2s[s] = bi1s[s];
                            bv1s[s] = v;       bi1s[s] = n;
                        } else if (v > bv2s[s]) {
                            bv2s[s] = v; bi2s[s] = n;
                        }
                        acc[t][j][q] = 0.f;
                    }
                }
            }
        }
    }

    // ---------------- negq --------------------------------------------------
    if (wn == 0) {
#pragma unroll
        for (int s = 0; s < 4; s++) {
            float v = ssqf[s];
            v += __shfl_xor_sync(0xffffffffu, v, 1);
            v += __shfl_xor_sync(0xffffffffu, v, 2);
            ssqf[s] = v;
        }
        if ((lid & 3) == 0) {
#pragma unroll
            for (int t = 0; t < 2; t++) {
                int p = wm * 32 + t * 16 + (lid >> 2);
                s_negq[p]     = -0.25f * sqrtf(ssqf[2 * t]);
                s_negq[p + 8] = -0.25f * sqrtf(ssqf[2 * t + 1]);
            }
        }
    }

    // ---------------- warp-level top-2 merge across lid&3 lanes -------------
#pragma unroll
    for (int s = 0; s < 4; s++) {
#pragma unroll
        for (int o = 1; o <= 2; o <<= 1) {
            float ov1 = __shfl_xor_sync(0xffffffffu, bv1s[s], o);
            float ov2 = __shfl_xor_sync(0xffffffffu, bv2s[s], o);
            int   oi1 = __shfl_xor_sync(0xffffffffu, bi1s[s], o);
            int   oi2 = __shfl_xor_sync(0xffffffffu, bi2s[s], o);
            if (ov1 > bv1s[s] || (ov1 == bv1s[s] && oi1 < bi1s[s])) {
                bv2s[s] = bv1s[s]; bi2s[s] = bi1s[s];
                bv1s[s] = ov1;     bi1s[s] = oi1;
            } else if (ov1 > bv2s[s] || (ov1 == bv2s[s] && oi1 < bi2s[s])) {
                bv2s[s] = ov1; bi2s[s] = oi1;
            }
            if (ov2 > bv2s[s] || (ov2 == bv2s[s] && oi2 < bi2s[s])) {
                bv2s[s] = ov2; bi2s[s] = oi2;
            }
        }
    }
    __syncthreads();    // GEMM fully done: A smem region now reusable
    Red* red = (Red*)dsm;
    if ((lid & 3) == 0) {
#pragma unroll
        for (int t = 0; t < 2; t++)
#pragma unroll
            for (int h = 0; h < 2; h++) {
                int s = 2 * t + h;
                int p = wm * 32 + t * 16 + (lid >> 2) + 8 * h;
                red->bv1[p][wn] = bv1s[s];
                red->bv2[p][wn] = bv2s[s];
                red->bi1[p][wn] = bi1s[s];
                red->bi2[p][wn] = bi2s[s];
            }
    }
    __syncthreads();

    if (tid < MT) {
        float B1 = -1e30f, B2 = -1e30f;
        int I1 = 0x7fffffff, I2 = 0x7fffffff;
#pragma unroll
        for (int col = 0; col < 8; col++) {
#pragma unroll
            for (int w = 0; w < 2; w++) {
                float v = w ? red->bv2[tid][col] : red->bv1[tid][col];
                int   i = w ? red->bi2[tid][col] : red->bi1[tid][col];
                if (v > B1 || (v == B1 && i < I1)) {
                    B2 = B1; I2 = I1; B1 = v; I1 = i;
                } else if (v > B2 || (v == B2 && i < I2)) {
                    B2 = v; I2 = i;
                }
            }
        }
        int bi = I1;
        if (B1 - B2 < MARGIN) {
            const float* xp = xb + tid;
            const float* d1 = g_dnorm + (size_t)I1 * CCH;
            const float* d2 = g_dnorm + (size_t)I2 * CCH;
            float s1 = 0.f, s2 = 0.f;
            for (int k = 0; k < CCH; k++) {
                float xv = xp[(size_t)k * HWV];
                s1 = fmaf(xv, d1[k], s1);
                s2 = fmaf(xv, d2[k], s2);
            }
            if (s2 > s1 || (s2 == s1 && I2 < I1)) bi = I2;
        }
        s_idx[tid] = bi;
        s_rep[tid] = (B1 > s_negq[tid]) ? 1 : 0;
    }
    __syncthreads();

    // ---------------- epilogue: gather + blend + coalesced writes ------------
    float (*rows)[65] = (float (*)[65])dsm;   // aliases A region (free now)
    float* outb = out + (size_t)b * CCH * HWV + hw0;
    for (int c0 = 0; c0 < CCH; c0 += 64) {
#pragma unroll
        for (int it = 0; it < 2; it++) {
            int lin = it * THREADS + tid;   // over [p:64][cq:16]
            int p = lin >> 4;
            int cq = (lin & 15) * 4;
            float4 v = *(const float4*)(dict + (size_t)s_idx[p] * CCH + c0 + cq);
            rows[p][cq + 0] = v.x;
            rows[p][cq + 1] = v.y;
            rows[p][cq + 2] = v.z;
            rows[p][cq + 3] = v.w;
        }
        __syncthreads();
#pragma unroll
        for (int it = 0; it < 8; it++) {
            int lin = it * THREADS + tid;   // over [c:64][p:64]
            int c = c0 + (lin >> 6);
            int p = lin & 63;
            float v = rows[p][c - c0];
            if (!s_rep[p]) v = xb[(size_t)c * HWV + p];
            outb[(size_t)c * HWV + p] = v;
        }
        __syncthreads();
    }
}

// ---------------- launch ------------------------------------------------------
extern "C" void kernel_launch(void* const* d_in, const int* in_sizes, int n_in,
                              void* d_out, int out_size) {
    const float* x;
    const float* nd;
    if (n_in >= 2 && in_sizes[0] == ND * CCH && in_sizes[1] != ND * CCH) {
        nd = (const float*)d_in[0];
        x  = (const float*)d_in[1];
    } else {
        x  = (const float*)d_in[0];
        nd = (const float*)d_in[1];
    }
    float* out = (float*)d_out;

    cudaFuncSetAttribute(negdict_mma, cudaFuncAttributeMaxDynamicSharedMemorySize,
                         229376);

    prep_dict<<<ND, 128>>>(nd);
    negdict_mma<<<NPX / MT, THREADS, 229376>>>(x, nd, out);
}

// round 11
// speedup vs baseline: 1.6957x; 1.3578x over previous
#include <cuda_runtime.h>
#include <cuda_fp16.h>
#include <math.h>
#include <stdint.h>

#define CCH 512
#define ND  512
#define HWV 4096
#define NPX 65536
#define MT  64
#define KCH 32
#define TOTCH 32          // 2 n-passes (256n) * 16 k-chunks
#define THREADS 512
#define MARGIN 1e-5f

#define SW64(o) ((o) ^ (((o) >> 3) & 0x30))

typedef unsigned int u32;

// ---------------- device scratch ----------------
// B stored as pre-swizzled 16KB chunk tiles: chunk cc = nt*16+kc, tile [256n][32k]
__device__ __align__(16) __half g_Bthi[TOTCH * 8192];
__device__ __align__(16) __half g_Btlo[TOTCH * 8192];
__device__ float g_dnorm[ND * CCH];

// ---------------- PTX helpers ----------------
__device__ __forceinline__ u32 smem_u32(const void* p) {
    u32 a;
    asm("{ .reg .u64 t; cvta.to.shared.u64 t, %1; cvt.u32.u64 %0, t; }" : "=r"(a) : "l"(p));
    return a;
}
#define MBAR_INIT(mb, c)  asm volatile("mbarrier.init.shared.b64 [%0], %1;" :: "r"(mb), "r"(c) : "memory")
#define FENCE_ASYNC()     asm volatile("fence.proxy.async.shared::cta;" ::: "memory")
#define MBAR_EXPECT_TX(mb, n) \
    asm volatile("mbarrier.arrive.expect_tx.shared.b64 _, [%0], %1;" :: "r"(mb), "r"(n) : "memory")
#define BULK_G2S(dst, src, sz, mb) \
    asm volatile("cp.async.bulk.shared::cta.global.mbarrier::complete_tx::bytes [%0], [%1], %2, [%3];" \
        :: "r"(dst), "l"(src), "r"(sz), "r"(mb) : "memory")

__device__ __forceinline__ void mbar_wait0(u32 mb) {
    u32 done;
    asm volatile(
        "{ .reg .pred p;\n\t"
        "mbarrier.try_wait.parity.acquire.cta.shared::cta.b64 p, [%1], 0;\n\t"
        "selp.b32 %0, 1, 0, p; }"
        : "=r"(done) : "r"(mb) : "memory");
    while (!done) {
        asm volatile(
            "{ .reg .pred p;\n\t"
            "mbarrier.try_wait.parity.acquire.cta.shared::cta.b64 p, [%1], 0, 0x989680;\n\t"
            "selp.b32 %0, 1, 0, p; }"
            : "=r"(done) : "r"(mb) : "memory");
    }
}

#define LDSM4(r, addr) \
    asm volatile("ldmatrix.sync.aligned.m8n8.x4.shared.b16 {%0,%1,%2,%3}, [%4];" \
        : "=r"((r)[0]), "=r"((r)[1]), "=r"((r)[2]), "=r"((r)[3]) : "r"(addr))

#define MMA16816(d, a, b0, b1) \
    asm volatile("mma.sync.aligned.m16n8k16.row.col.f32.f16.f16.f32 " \
        "{%0,%1,%2,%3},{%4,%5,%6,%7},{%8,%9},{%0,%1,%2,%3};" \
        : "+f"((d)[0]), "+f"((d)[1]), "+f"((d)[2]), "+f"((d)[3]) \
        : "r"((a)[0]), "r"((a)[1]), "r"((a)[2]), "r"((a)[3]), "r"(b0), "r"(b1))

#define STS128(addr, v) \
    asm volatile("st.shared.v4.b32 [%0], {%1,%2,%3,%4};" \
        :: "r"(addr), "r"((v).x), "r"((v).y), "r"((v).z), "r"((v).w) : "memory")

// ---------------- prep: dict -> dnorm + pre-swizzled fp16 hi/lo chunk tiles --
__global__ void prep_dict(const float* __restrict__ dict) {
    int n = blockIdx.x;
    const float* row = dict + n * CCH;
    float s = 0.f;
    for (int k = threadIdx.x; k < CCH; k += 128) {
        float v = row[k];
        s = fmaf(v, v, s);
    }
#pragma unroll
    for (int o = 16; o; o >>= 1) s += __shfl_xor_sync(0xffffffffu, s, o);
    __shared__ float red[4];
    if ((threadIdx.x & 31) == 0) red[threadIdx.x >> 5] = s;
    __syncthreads();
    float norm = sqrtf(red[0] + red[1] + red[2] + red[3]);
    int nt = n >> 8;
    int r = n & 255;
    for (int k = threadIdx.x; k < CCH; k += 128) {
        float v = row[k] / norm;
        g_dnorm[n * CCH + k] = v;
        __half h = __float2half(v);
        __half l = __float2half(v - __half2float(h));
        int kc = k >> 5;
        int kin = k & 31;
        u32 off = SW64((u32)(r * 64 + kin * 2));     // byte offset in 16KB tile
        size_t idx = (size_t)(nt * 16 + kc) * 8192 + (off >> 1);
        g_Bthi[idx] = h;
        g_Btlo[idx] = l;
    }
}

// reduction overlay (aliased onto the A smem region after the GEMM)
struct Red {
    float bv1[MT][8]; float bv2[MT][8];
    int   bi1[MT][8]; int   bi2[MT][8];
};

// ---------------- main: fused convert + persistent-A split-fp16 GEMM --------
__global__ void __launch_bounds__(THREADS, 1)
negdict_mma(const float* __restrict__ x, const float* __restrict__ dict,
            float* __restrict__ out) {
    // dyn smem: Ahi 64KB | Alo 64KB | B ring 3 x 32KB  = 224KB
    extern __shared__ __align__(16) char dsm[];
    __shared__ float s_negq[MT];
    __shared__ int s_idx[MT];
    __shared__ int s_rep[MT];
    __shared__ __align__(8) unsigned long long s_mbar[TOTCH];

    const int tid = threadIdx.x;
    const int wid = tid >> 5;
    const int lid = tid & 31;
    const int wm = wid >> 3;          // 0..1 : 32 px each
    const int wn = wid & 7;           // 0..7 : 32 n each (per n-pass)
    const int pxbase = blockIdx.x * MT;
    const int b = pxbase >> 12;
    const int hw0 = pxbase & 4095;
    const float* xb = x + (size_t)b * CCH * HWV + hw0;

    const u32 sA = smem_u32(dsm);              // hi tiles: 16 x 4KB
    const u32 sAlo = sA + 65536;               // lo tiles
    const u32 sB = sA + 131072;                // ring: buf*32KB (hi 16KB | lo 16KB)
    const u32 mbar0 = smem_u32(&s_mbar[0]);

    // ldmatrix lane offsets (A tile: 64px x 32k, 64B rows; B tile: 256n x 32k)
    u32 offA[2], offB[2];
#pragma unroll
    for (int t = 0; t < 2; t++) {
        int rowA = wm * 32 + t * 16 + (lid & 7) + 8 * ((lid >> 3) & 1);
        offA[t] = SW64((u32)(rowA * 64 + ((lid >> 4) << 4)));
    }
#pragma unroll
    for (int g = 0; g < 2; g++) {
        int rowB = wn * 32 + g * 16 + (lid & 7) + 8 * (lid >> 4);
        offB[g] = SW64((u32)(rowB * 64 + (((lid >> 3) & 1) << 4)));
    }

    float acc[2][4][4];
#pragma unroll
    for (int t = 0; t < 2; t++)
#pragma unroll
        for (int j = 0; j < 4; j++)
#pragma unroll
            for (int q = 0; q < 4; q++) acc[t][j][q] = 0.f;

    float bv1s[4], bv2s[4];
    int bi1s[4], bi2s[4];
#pragma unroll
    for (int s = 0; s < 4; s++) {
        bv1s[s] = -1e30f; bv2s[s] = -1e30f;
        bi1s[s] = 0x7fffffff; bi2s[s] = 0x7fffffff;
    }
    float ssqf[4] = {0.f, 0.f, 0.f, 0.f};

    // x prefetch mapping (tid<256): px = tid&63, kh = (tid>>6)&3 (8 k each)
    const int px_l = tid & 63;
    const int kh = (tid >> 6) & 3;
    const bool xload = (tid < 256);
    float xr[8];

    auto ldx = [&](int cc) {
        if (!xload) return;
        int k0 = (cc & 15) * KCH + kh * 8;
#pragma unroll
        for (int i = 0; i < 8; i++) xr[i] = xb[(size_t)(k0 + i) * HWV + px_l];
    };
    auto cvtsts = [&](int cc) {
        if (!xload) return;
        union { __half2 h2[4]; uint4 v; } hi, lo;
#pragma unroll
        for (int i = 0; i < 4; i++) {
            __half h0 = __float2half(xr[2 * i]);
            __half h1 = __float2half(xr[2 * i + 1]);
            hi.h2[i] = __halves2half2(h0, h1);
            lo.h2[i] = __halves2half2(
                __float2half(xr[2 * i]     - __half2float(h0)),
                __float2half(xr[2 * i + 1] - __half2float(h1)));
        }
        u32 dst = (u32)((cc & 15) * 4096) + SW64((u32)(px_l * 64 + kh * 16));
        STS128(sA + dst, hi.v);
        STS128(sAlo + dst, lo.v);
    };
    auto issueB = [&](int cc) {    // single thread; 2 bulk copies of 16KB
        u32 bufb = sB + (cc % 3) * 32768;
        u32 mb = mbar0 + cc * 8;
        MBAR_EXPECT_TX(mb, 32768u);
        BULK_G2S(bufb,         (const char*)g_Bthi + (size_t)cc * 16384, 16384u, mb);
        BULK_G2S(bufb + 16384, (const char*)g_Btlo + (size_t)cc * 16384, 16384u, mb);
    };

    // prologue: init mbarriers (+ async-proxy fence), build A tile 0, start B pipeline
    if (tid == 0) {
#pragma unroll
        for (int c = 0; c < TOTCH; c++) MBAR_INIT(mbar0 + c * 8, 1);
        FENCE_ASYNC();
    }
    ldx(0);
    __syncthreads();
    if (tid == 0) { issueB(0); issueB(1); }
    cvtsts(0);
    __syncthreads();    // A tile 0 writes visible before chunk-0 LDSM reads

    for (int cc = 0; cc < TOTCH; cc++) {
        if (tid == 0 && cc + 2 < TOTCH) issueB(cc + 2);   // buf (cc+2)%3 free since end of cc-1
        if (cc + 1 < 16) ldx(cc + 1);
        mbar_wait0(mbar0 + cc * 8);

        const u32 abase = sA + (cc & 15) * 4096;
        const u32 albase = sAlo + (cc & 15) * 4096;
        const u32 bbase = sB + (cc % 3) * 32768;

        __half2 cA[2], cB[2];
        cA[0] = cA[1] = cB[0] = cB[1] = __halves2half2(__float2half(0.f), __float2half(0.f));

#pragma unroll
        for (int s = 0; s < 2; s++) {
            u32 kx = (u32)(s << 5);
            u32 Ah[2][4], Al[2][4], Bh[2][4], Bl[2][4];
#pragma unroll
            for (int t = 0; t < 2; t++) {
                LDSM4(Ah[t], abase + (offA[t] ^ kx));
                LDSM4(Al[t], albase + (offA[t] ^ kx));
            }
#pragma unroll
            for (int g = 0; g < 2; g++) {
                LDSM4(Bh[g], bbase + (offB[g] ^ kx));
                LDSM4(Bl[g], bbase + 16384 + (offB[g] ^ kx));
            }
            if (cc < 16 && wn == 0) {       // ||x||^2 from hi fragments (n-pass 0)
#pragma unroll
                for (int t = 0; t < 2; t++) {
                    __half2 a0 = *(__half2*)&Ah[t][0];
                    __half2 a2 = *(__half2*)&Ah[t][2];
                    __half2 a1 = *(__half2*)&Ah[t][1];
                    __half2 a3 = *(__half2*)&Ah[t][3];
                    cA[t] = __hfma2(a0, a0, cA[t]);
                    cA[t] = __hfma2(a2, a2, cA[t]);
                    cB[t] = __hfma2(a1, a1, cB[t]);
                    cB[t] = __hfma2(a3, a3, cB[t]);
                }
            }
#pragma unroll
            for (int t = 0; t < 2; t++)
#pragma unroll
                for (int j = 0; j < 4; j++)
                    MMA16816(acc[t][j], Ah[t], Bh[j >> 1][(j & 1) * 2], Bh[j >> 1][(j & 1) * 2 + 1]);
#pragma unroll
            for (int t = 0; t < 2; t++)
#pragma unroll
                for (int j = 0; j < 4; j++)
                    MMA16816(acc[t][j], Ah[t], Bl[j >> 1][(j & 1) * 2], Bl[j >> 1][(j & 1) * 2 + 1]);
#pragma unroll
            for (int t = 0; t < 2; t++)
#pragma unroll
                for (int j = 0; j < 4; j++)
                    MMA16816(acc[t][j], Al[t], Bh[j >> 1][(j & 1) * 2], Bh[j >> 1][(j & 1) * 2 + 1]);
        }

        if (cc < 16 && wn == 0) {
#pragma unroll
            for (int t = 0; t < 2; t++) {
                ssqf[2 * t]     += __low2float(cA[t]) + __high2float(cA[t]);
                ssqf[2 * t + 1] += __low2float(cB[t]) + __high2float(cB[t]);
            }
        }
        if (cc + 1 < 16) cvtsts(cc + 1);

        if ((cc & 15) == 15) {              // fold n-pass (256n) into per-lane top-2
            int nt = cc >> 4;
            int nbase = nt * 256 + wn * 32;
#pragma unroll
            for (int j = 0; j < 4; j++) {
                int nb = nbase + (j >> 1) * 16 + (j & 1) * 8 + 2 * (lid & 3);
#pragma unroll
                for (int t = 0; t < 2; t++) {
#pragma unroll
                    for (int q = 0; q < 4; q++) {
                        int s = 2 * t + (q >> 1);
                        int n = nb + (q & 1);
                        float v = acc[t][j][q];
                        if (v > bv1s[s]) {
                            bv2s[s] = bv1s[s]; bi2s[s] = bi1s[s];
                            bv1s[s] = v;       bi1s[s] = n;
                        } else if (v > bv2s[s]) {
                            bv2s[s] = v; bi2s[s] = n;
                        }
                        acc[t][j][q] = 0.f;
                    }
                }
            }
        }
        __syncthreads();    // reads of buf cc%3 done; A tile cc+1 writes visible
    }

    // ---------------- negq --------------------------------------------------
    if (wn == 0) {
#pragma unroll
        for (int s = 0; s < 4; s++) {
            float v = ssqf[s];
            v += __shfl_xor_sync(0xffffffffu, v, 1);
            v += __shfl_xor_sync(0xffffffffu, v, 2);
            ssqf[s] = v;
        }
        if ((lid & 3) == 0) {
#pragma unroll
            for (int t = 0; t < 2; t++) {
                int p = wm * 32 + t * 16 + (lid >> 2);
                s_negq[p]     = -0.25f * sqrtf(ssqf[2 * t]);
                s_negq[p + 8] = -0.25f * sqrtf(ssqf[2 * t + 1]);
            }
        }
    }

    // ---------------- warp-level top-2 merge across lid&3 lanes -------------
#pragma unroll
    for (int s = 0; s < 4; s++) {
#pragma unroll
        for (int o = 1; o <= 2; o <<= 1) {
            float ov1 = __shfl_xor_sync(0xffffffffu, bv1s[s], o);
            float ov2 = __shfl_xor_sync(0xffffffffu, bv2s[s], o);
            int   oi1 = __shfl_xor_sync(0xffffffffu, bi1s[s], o);
            int   oi2 = __shfl_xor_sync(0xffffffffu, bi2s[s], o);
            if (ov1 > bv1s[s] || (ov1 == bv1s[s] && oi1 < bi1s[s])) {
                bv2s[s] = bv1s[s]; bi2s[s] = bi1s[s];
                bv1s[s] = ov1;     bi1s[s] = oi1;
            } else if (ov1 > bv2s[s] || (ov1 == bv2s[s] && oi1 < bi2s[s])) {
                bv2s[s] = ov1; bi2s[s] = oi1;
            }
            if (ov2 > bv2s[s] || (ov2 == bv2s[s] && oi2 < bi2s[s])) {
                bv2s[s] = ov2; bi2s[s] = oi2;
            }
        }
    }
    __syncthreads();    // GEMM fully done: A smem region now reusable
    Red* red = (Red*)dsm;
    if ((lid & 3) == 0) {
#pragma unroll
        for (int t = 0; t < 2; t++)
#pragma unroll
            for (int h = 0; h < 2; h++) {
                int s = 2 * t + h;
                int p = wm * 32 + t * 16 + (lid >> 2) + 8 * h;
                red->bv1[p][wn] = bv1s[s];
                red->bv2[p][wn] = bv2s[s];
                red->bi1[p][wn] = bi1s[s];
                red->bi2[p][wn] = bi2s[s];
            }
    }
    __syncthreads();

    if (tid < MT) {
        float B1 = -1e30f, B2 = -1e30f;
        int I1 = 0x7fffffff, I2 = 0x7fffffff;
#pragma unroll
        for (int col = 0; col < 8; col++) {
#pragma unroll
            for (int w = 0; w < 2; w++) {
                float v = w ? red->bv2[tid][col] : red->bv1[tid][col];
                int   i = w ? red->bi2[tid][col] : red->bi1[tid][col];
                if (v > B1 || (v == B1 && i < I1)) {
                    B2 = B1; I2 = I1; B1 = v; I1 = i;
                } else if (v > B2 || (v == B2 && i < I2)) {
                    B2 = v; I2 = i;
                }
            }
        }
        int bi = I1;
        if (B1 - B2 < MARGIN) {
            const float* xp = xb + tid;
            const float* d1 = g_dnorm + (size_t)I1 * CCH;
            const float* d2 = g_dnorm + (size_t)I2 * CCH;
            float s1 = 0.f, s2 = 0.f;
            for (int k = 0; k < CCH; k++) {
                float xv = xp[(size_t)k * HWV];
                s1 = fmaf(xv, d1[k], s1);
                s2 = fmaf(xv, d2[k], s2);
            }
            if (s2 > s1 || (s2 == s1 && I2 < I1)) bi = I2;
        }
        s_idx[tid] = bi;
        s_rep[tid] = (B1 > s_negq[tid]) ? 1 : 0;
    }
    __syncthreads();

    // ---------------- epilogue: gather + blend + coalesced writes ------------
    float (*rows)[65] = (float (*)[65])dsm;   // aliases A region (free now)
    float* outb = out + (size_t)b * CCH * HWV + hw0;
    for (int c0 = 0; c0 < CCH; c0 += 64) {
#pragma unroll
        for (int it = 0; it < 2; it++) {
            int lin = it * THREADS + tid;   // over [p:64][cq:16]
            int p = lin >> 4;
            int cq = (lin & 15) * 4;
            float4 v = *(const float4*)(dict + (size_t)s_idx[p] * CCH + c0 + cq);
            rows[p][cq + 0] = v.x;
            rows[p][cq + 1] = v.y;
            rows[p][cq + 2] = v.z;
            rows[p][cq + 3] = v.w;
        }
        __syncthreads();
#pragma unroll
        for (int it = 0; it < 8; it++) {
            int lin = it * THREADS + tid;   // over [c:64][p:64]
            int c = c0 + (lin >> 6);
            int p = lin & 63;
            float v = rows[p][c - c0];
            if (!s_rep[p]) v = xb[(size_t)c * HWV + p];
            outb[(size_t)c * HWV + p] = v;
        }
        __syncthreads();
    }
}

// ---------------- launch ------------------------------------------------------
extern "C" void kernel_launch(void* const* d_in, const int* in_sizes, int n_in,
                              void* d_out, int out_size) {
    const float* x;
    const float* nd;
    if (n_in >= 2 && in_sizes[0] == ND * CCH && in_sizes[1] != ND * CCH) {
        nd = (const float*)d_in[0];
        x  = (const float*)d_in[1];
    } else {
        x  = (const float*)d_in[0];
        nd = (const float*)d_in[1];
    }
    float* out = (float*)d_out;

    cudaFuncSetAttribute(negdict_mma, cudaFuncAttributeMaxDynamicSharedMemorySize,
                         229376);

    prep_dict<<<ND, 128>>>(nd);
    negdict_mma<<<NPX / MT, THREADS, 229376>>>(x, nd, out);
}